// round 9
// baseline (speedup 1.0000x reference)
#include <cuda_runtime.h>

#define BB 16
#define DD 1024
#define HH 16
#define HDIM 64
#define TPAST 1023
#define SENC 1024
#define FFD 4096
#define ASCALE 0.125f
#define LN_EPS 1e-5f
#define VOUT 20

// ------------------------- device scratch (static, no allocation) ----------
__device__ float g_x[BB * DD];              // residual stream
__device__ float g_qkv[3 * BB * DD];        // q | k_new | v_new
__device__ float g_attn[BB * DD];           // attn output / proj input
__device__ float g_qc[BB * DD];             // cross-attn query
__device__ float g_qb[BB * HH];             // q . bk per head
__device__ float g_fold[BB * DD * HH];      // folded K direction [b][e][h]
__device__ float g_sc[BB * HH * SENC];      // cross scores -> probs in place
__device__ float g_ctx[BB * HH * DD];       // cross context [b][h][e]
__device__ float g_hbuf[BB * FFD];          // FFN hidden
__device__ float g_part[4194304];           // k-split GEMM partials (16 MB)
__device__ float g_am[BB * HH * 4];         // self-attn chunk max
__device__ float g_al[BB * HH * 4];         // self-attn chunk denom
__device__ float g_ac[BB * HH * 4 * HDIM];  // self-attn chunk numerators

struct W3 { const float* w[3]; };
struct R3 { const float* bias[3]; float* out[3]; };

// ------------------------- init: copy input x -> g_x -----------------------
__global__ void __launch_bounds__(256) init_x(const float* __restrict__ x) {
    int i = blockIdx.x * 256 + threadIdx.x;
    if (i < BB * DD) g_x[i] = x[i];
}

// ------------------------- k-split GEMM v2 ---------------------------------
// grid (KS, N/256, nmats), block 256. Thread owns ONE n-col for all 16 b.
// Large kc (32..128) -> small partial buffers (KS*16*N), L2-resident.
__global__ void __launch_bounds__(256) gemm2(const float* __restrict__ x, W3 mats,
                                             float* __restrict__ part,
                                             int N, int K, int kc) {
    __shared__ float sx[2048];                 // up to 16 x 128
    const int k0 = blockIdx.x * kc;
    const float* __restrict__ W = mats.w[blockIdx.z];
    const int tid = threadIdx.x;
    for (int i = tid; i < BB * kc; i += 256) {
        int b = i / kc, kk = i - b * kc;
        sx[b * kc + kk] = x[(size_t)b * K + k0 + kk];
    }
    __syncthreads();
    const int n = blockIdx.y * 256 + tid;
    float acc[BB];
#pragma unroll
    for (int b = 0; b < BB; b++) acc[b] = 0.f;
#pragma unroll 4
    for (int kk = 0; kk < kc; kk++) {
        float w = W[(size_t)(k0 + kk) * N + n];
#pragma unroll
        for (int b = 0; b < BB; b++) acc[b] = fmaf(sx[b * kc + kk], w, acc[b]);
    }
    float* pb = part + (size_t)(blockIdx.z * gridDim.x + blockIdx.x) * BB * N;
#pragma unroll
    for (int b = 0; b < BB; b++) pb[(size_t)b * N + n] = acc[b];
}

// ---------------- folded V projection v2 (per-head K) ----------------------
// grid (KS, 4), block 256. Block's 256 n-cols span 4 heads (hbase..hbase+3).
// out[b,n] = sum_e ctx[b, h(n), e] * wv[e, n]
__global__ void __launch_bounds__(256) vproj2(const float* __restrict__ W,
                                              float* __restrict__ part, int kc) {
    __shared__ float sx[2048];                 // [b][h4][kk], 16*4*kc (kc<=32)
    const int k0 = blockIdx.x * kc;
    const int hbase = blockIdx.y * 4;
    const int tid = threadIdx.x;
    const int tot = BB * 4 * kc;
    for (int i = tid; i < tot; i += 256) {
        int b = i / (4 * kc), r = i - b * 4 * kc;
        int h = r / kc, kk = r - h * kc;
        sx[i] = g_ctx[((size_t)(b * HH + hbase + h)) * DD + k0 + kk];
    }
    __syncthreads();
    const int n = blockIdx.y * 256 + tid;
    const int h4 = tid >> 6;
    float acc[BB];
#pragma unroll
    for (int b = 0; b < BB; b++) acc[b] = 0.f;
#pragma unroll 4
    for (int kk = 0; kk < kc; kk++) {
        float w = W[(size_t)(k0 + kk) * DD + n];
#pragma unroll
        for (int b = 0; b < BB; b++)
            acc[b] = fmaf(sx[(b * 4 + h4) * kc + kk], w, acc[b]);
    }
    float* pb = part + (size_t)blockIdx.x * BB * DD;
#pragma unroll
    for (int b = 0; b < BB; b++) pb[(size_t)b * DD + n] = acc[b];
}

// ------------------------- reduce partials + bias (+relu) ------------------
// grid ((16*N)/1024, 1, nz), block 256
__global__ void __launch_bounds__(256) reduce_bias(const float* __restrict__ part, R3 p,
                                                   int N, int KS, int relu) {
    const int z = blockIdx.z;
    const float* pp = part + (size_t)z * KS * BB * N;
    int idx = (blockIdx.x * 256 + threadIdx.x) * 4;
    int b = idx / N, n = idx - b * N;
    float4 a = make_float4(0.f, 0.f, 0.f, 0.f);
#pragma unroll 8
    for (int ks = 0; ks < KS; ks++) {
        float4 v = *(const float4*)(pp + ((size_t)ks * BB + b) * N + n);
        a.x += v.x; a.y += v.y; a.z += v.z; a.w += v.w;
    }
    float4 bi = *(const float4*)(p.bias[z] + n);
    a.x += bi.x; a.y += bi.y; a.z += bi.z; a.w += bi.w;
    if (relu) {
        a.x = fmaxf(a.x, 0.f); a.y = fmaxf(a.y, 0.f);
        a.z = fmaxf(a.z, 0.f); a.w = fmaxf(a.w, 0.f);
    }
    *(float4*)(p.out[z] + (size_t)b * N + n) = a;
}

// ---------------- reduce + bias + residual + LayerNorm -> g_x --------------
__global__ void __launch_bounds__(1024) reduce_ln(const float* __restrict__ part, int KS,
                                                  const float* __restrict__ bias,
                                                  const float* __restrict__ gam,
                                                  const float* __restrict__ bet) {
    const int b = blockIdx.x, n = threadIdx.x;
    float v = 0.f;
#pragma unroll 8
    for (int ks = 0; ks < KS; ks++) v += part[((size_t)ks * BB + b) * DD + n];
    v += bias[n] + g_x[b * DD + n];
    float s = v, q = v * v;
#pragma unroll
    for (int o = 16; o; o >>= 1) {
        s += __shfl_xor_sync(0xffffffffu, s, o);
        q += __shfl_xor_sync(0xffffffffu, q, o);
    }
    __shared__ float s1[32], s2[32], mv[2];
    int w = n >> 5, ln = n & 31;
    if (ln == 0) { s1[w] = s; s2[w] = q; }
    __syncthreads();
    if (w == 0) {
        float a = s1[ln], c = s2[ln];
#pragma unroll
        for (int o = 16; o; o >>= 1) {
            a += __shfl_xor_sync(0xffffffffu, a, o);
            c += __shfl_xor_sync(0xffffffffu, c, o);
        }
        if (ln == 0) {
            float mean = a * (1.f / DD);
            mv[0] = mean;
            mv[1] = rsqrtf(c * (1.f / DD) - mean * mean + LN_EPS);
        }
    }
    __syncthreads();
    g_x[b * DD + n] = (v - mv[0]) * mv[1] * gam[n] + bet[n];
}

// ---------------- reduce cross q + per-head q.bk ---------------------------
__global__ void __launch_bounds__(1024) reduce_qc(const float* __restrict__ part, int KS,
                                                  const float* __restrict__ bias,
                                                  const float* __restrict__ bk) {
    const int b = blockIdx.x, n = threadIdx.x;
    float v = 0.f;
#pragma unroll 8
    for (int ks = 0; ks < KS; ks++) v += part[((size_t)ks * BB + b) * DD + n];
    v += bias[n];
    g_qc[b * DD + n] = v;
    float pb = v * bk[n];
#pragma unroll
    for (int o = 16; o; o >>= 1) pb += __shfl_xor_sync(0xffffffffu, pb, o);
    __shared__ float sw[32];
    if ((n & 31) == 0) sw[n >> 5] = pb;
    __syncthreads();
    if (n < HH) g_qb[b * HH + n] = sw[2 * n] + sw[2 * n + 1];
}

// ---------------- self-attention over KV cache (split-T) -------------------
// grid (16, 16, 4), block 256 (8 warps). Warp handles 32 t-values.
__global__ void __launch_bounds__(256) attn_part(const float* __restrict__ kcache,
                                                 const float* __restrict__ vcache) {
    const int b = blockIdx.x, h = blockIdx.y, c = blockIdx.z;
    const int tid = threadIdx.x, warp = tid >> 5, lane = tid & 31;
    const int bh = b * HH + h;
    const float* qp = g_qkv + b * DD + h * HDIM + lane * 2;
    const float q0 = qp[0], q1 = qp[1];
    const size_t base = (size_t)bh * TPAST * HDIM;
    const float* knew = g_qkv + BB * DD + b * DD + h * HDIM + lane * 2;
    const float* vnew = g_qkv + 2 * BB * DD + b * DD + h * HDIM + lane * 2;
    const int t0 = c * 256 + warp;
    float p[32];
#pragma unroll
    for (int j = 0; j < 32; j++) {
        int t = t0 + j * 8;
        const float* kp = (t < TPAST) ? (kcache + base + (size_t)t * HDIM + lane * 2) : knew;
        float2 kv = *(const float2*)kp;
        float s = fmaf(q0, kv.x, q1 * kv.y);
#pragma unroll
        for (int o = 16; o; o >>= 1) s += __shfl_xor_sync(0xffffffffu, s, o);
        p[j] = s * ASCALE;
    }
    float m = p[0];
#pragma unroll
    for (int j = 1; j < 32; j++) m = fmaxf(m, p[j]);
    float lsum = 0.f, a0 = 0.f, a1 = 0.f;
#pragma unroll
    for (int j = 0; j < 32; j++) {
        int t = t0 + j * 8;
        const float* vp = (t < TPAST) ? (vcache + base + (size_t)t * HDIM + lane * 2) : vnew;
        float2 vv = *(const float2*)vp;
        float e = __expf(p[j] - m);
        lsum += e;
        a0 = fmaf(e, vv.x, a0);
        a1 = fmaf(e, vv.y, a1);
    }
    __shared__ float sm[8], sl[8], sa[8][64];
    if (lane == 0) { sm[warp] = m; sl[warp] = lsum; }
    sa[warp][lane * 2] = a0;
    sa[warp][lane * 2 + 1] = a1;
    __syncthreads();
    if (tid < 64) {
        float M = sm[0];
#pragma unroll
        for (int w = 1; w < 8; w++) M = fmaxf(M, sm[w]);
        float L = 0.f, o = 0.f;
#pragma unroll
        for (int w = 0; w < 8; w++) {
            float cf = __expf(sm[w] - M);
            L = fmaf(cf, sl[w], L);
            o = fmaf(cf, sa[w][tid], o);
        }
        g_ac[(bh * 4 + c) * 64 + tid] = o;
        if (tid == 0) { g_am[bh * 4 + c] = M; g_al[bh * 4 + c] = L; }
    }
}

// ---------------- merge self-attn chunks -> g_attn -------------------------
__global__ void __launch_bounds__(64) attn_merge() {
    const int bh = blockIdx.x, d = threadIdx.x;
    float M = g_am[bh * 4];
#pragma unroll
    for (int c = 1; c < 4; c++) M = fmaxf(M, g_am[bh * 4 + c]);
    float L = 0.f, o = 0.f;
#pragma unroll
    for (int c = 0; c < 4; c++) {
        float cf = __expf(g_am[bh * 4 + c] - M);
        L = fmaf(cf, g_al[bh * 4 + c], L);
        o = fmaf(cf, g_ac[(bh * 4 + c) * 64 + d], o);
    }
    int b = bh >> 4, h = bh & 15;
    g_attn[b * DD + h * HDIM + d] = o / L;
}

// ---------------- fold K projection: g[b][e][h] ----------------------------
__global__ void __launch_bounds__(256) fold_g(const float* __restrict__ wk) {
    const int b = blockIdx.y;
    const int e0 = blockIdx.x * 64;
    const int tid = threadIdx.x, warp = tid >> 5, lane = tid & 31;
    __shared__ float sq[DD];
    for (int i = tid; i < DD; i += 256) sq[i] = g_qc[b * DD + i];
    __syncthreads();
#pragma unroll
    for (int j = 0; j < 8; j++) {
        int e = e0 + warp * 8 + j;
        const float* wr = wk + (size_t)e * DD;
        float gval = 0.f;
#pragma unroll
        for (int h = 0; h < HH; h++) {
            float s = fmaf(wr[h * 64 + lane], sq[h * 64 + lane],
                           wr[h * 64 + 32 + lane] * sq[h * 64 + 32 + lane]);
#pragma unroll
            for (int o = 16; o; o >>= 1) s += __shfl_xor_sync(0xffffffffu, s, o);
            if (lane == h) gval = s;
        }
        if (lane < HH) g_fold[((size_t)b * DD + e) * HH + lane] = gval;
    }
}

// ---------------- cross scores: enc . g + qb -------------------------------
__global__ void __launch_bounds__(256) cross_scores(const float* __restrict__ enc) {
    const int b = blockIdx.y;
    const int s0 = blockIdx.x * 64;
    const int tid = threadIdx.x;
    const int s_loc = tid >> 2, hg = tid & 3;
    __shared__ float se[64][68];
    float acc[4] = {0.f, 0.f, 0.f, 0.f};
    for (int ec = 0; ec < 16; ec++) {
        int e0 = ec * 64;
        for (int i = tid; i < 1024; i += 256) {
            int r = i >> 4, c4 = (i & 15) * 4;
            float4 v = *(const float4*)(enc + ((size_t)(b * SENC + s0 + r)) * DD + e0 + c4);
            *(float4*)&se[r][c4] = v;
        }
        __syncthreads();
        const float* gf = g_fold + ((size_t)b * DD + e0) * HH + hg * 4;
#pragma unroll 4
        for (int e = 0; e < 64; e++) {
            float4 g4 = *(const float4*)(gf + e * HH);
            float ev = se[s_loc][e];
            acc[0] = fmaf(ev, g4.x, acc[0]);
            acc[1] = fmaf(ev, g4.y, acc[1]);
            acc[2] = fmaf(ev, g4.z, acc[2]);
            acc[3] = fmaf(ev, g4.w, acc[3]);
        }
        __syncthreads();
    }
    int s = s0 + s_loc;
#pragma unroll
    for (int i = 0; i < 4; i++) {
        int h = hg * 4 + i;
        g_sc[((size_t)(b * HH + h)) * SENC + s] = (acc[i] + g_qb[b * HH + h]) * ASCALE;
    }
}

// ---------------- softmax over s (in place) --------------------------------
__global__ void __launch_bounds__(256) softmax_sc() {
    const int bh = blockIdx.x, tid = threadIdx.x;
    float* row = g_sc + (size_t)bh * SENC;
    float4 v = *(float4*)(row + tid * 4);
    float m = fmaxf(fmaxf(v.x, v.y), fmaxf(v.z, v.w));
#pragma unroll
    for (int o = 16; o; o >>= 1) m = fmaxf(m, __shfl_xor_sync(0xffffffffu, m, o));
    __shared__ float sh[8], sh2[8];
    int w = tid >> 5, ln = tid & 31;
    if (ln == 0) sh[w] = m;
    __syncthreads();
    float M = sh[0];
#pragma unroll
    for (int i = 1; i < 8; i++) M = fmaxf(M, sh[i]);
    float e0 = __expf(v.x - M), e1 = __expf(v.y - M);
    float e2 = __expf(v.z - M), e3 = __expf(v.w - M);
    float s = e0 + e1 + e2 + e3;
#pragma unroll
    for (int o = 16; o; o >>= 1) s += __shfl_xor_sync(0xffffffffu, s, o);
    if (ln == 0) sh2[w] = s;
    __syncthreads();
    float S = sh2[0];
#pragma unroll
    for (int i = 1; i < 8; i++) S += sh2[i];
    float r = 1.f / S;
    *(float4*)(row + tid * 4) = make_float4(e0 * r, e1 * r, e2 * r, e3 * r);
}

// ---------------- cross context: ctx[b][h][e] = sum_s p * enc --------------
__global__ void __launch_bounds__(256) cross_ctx(const float* __restrict__ enc) {
    const int b = blockIdx.y;
    const int e0 = blockIdx.x * 64;
    const int tid = threadIdx.x;
    const int e_loc = tid & 63, hg = tid >> 6;
    __shared__ float sp[16][65];
    float acc[4] = {0.f, 0.f, 0.f, 0.f};
    for (int sc = 0; sc < 16; sc++) {
        int s0 = sc * 64;
        for (int i = tid; i < 1024; i += 256) {
            int h = i >> 6, sl = i & 63;
            sp[h][sl] = g_sc[((size_t)(b * HH + h)) * SENC + s0 + sl];
        }
        __syncthreads();
        const float* ep = enc + ((size_t)(b * SENC + s0)) * DD + e0 + e_loc;
#pragma unroll 4
        for (int sl = 0; sl < 64; sl++) {
            float ev = ep[(size_t)sl * DD];
#pragma unroll
            for (int i = 0; i < 4; i++) acc[i] = fmaf(ev, sp[hg * 4 + i][sl], acc[i]);
        }
        __syncthreads();
    }
#pragma unroll
    for (int i = 0; i < 4; i++)
        g_ctx[((size_t)(b * HH + hg * 4 + i)) * DD + e0 + e_loc] = acc[i];
}

// ---------------- final logits ---------------------------------------------
__global__ void __launch_bounds__(256) final_logits(const float* __restrict__ wout,
                                                    const float* __restrict__ bout,
                                                    float* __restrict__ out) {
    const int b = blockIdx.x, v = blockIdx.y, tid = threadIdx.x;
    float s = 0.f;
    for (int d = tid; d < DD; d += 256) s = fmaf(g_x[b * DD + d], wout[d * VOUT + v], s);
#pragma unroll
    for (int o = 16; o; o >>= 1) s += __shfl_xor_sync(0xffffffffu, s, o);
    __shared__ float sw[8];
    if ((tid & 31) == 0) sw[tid >> 5] = s;
    __syncthreads();
    if (tid == 0) {
        float t = sw[0];
#pragma unroll
        for (int i = 1; i < 8; i++) t += sw[i];
        out[b * VOUT + v] = t + bout[v];
    }
}

// ===========================================================================
extern "C" void kernel_launch(void* const* d_in, const int* in_sizes, int n_in,
                              void* d_out, int out_size) {
    const float* x      = (const float*)d_in[0];
    const float* enc    = (const float*)d_in[1];
    const float* kcache = (const float*)d_in[2];
    const float* vcache = (const float*)d_in[3];
    const float* wq_s = (const float*)d_in[4];
    const float* bq_s = (const float*)d_in[5];
    const float* wk_s = (const float*)d_in[6];
    const float* bk_s = (const float*)d_in[7];
    const float* wv_s = (const float*)d_in[8];
    const float* bv_s = (const float*)d_in[9];
    const float* wo_s = (const float*)d_in[10];
    const float* bo_s = (const float*)d_in[11];
    const float* wq_c = (const float*)d_in[12];
    const float* bq_c = (const float*)d_in[13];
    const float* wk_c = (const float*)d_in[14];
    const float* bk_c = (const float*)d_in[15];
    const float* wv_c = (const float*)d_in[16];
    const float* bv_c = (const float*)d_in[17];
    const float* wo_c = (const float*)d_in[18];
    const float* bo_c = (const float*)d_in[19];
    const float* w1   = (const float*)d_in[20];
    const float* b1   = (const float*)d_in[21];
    const float* w2   = (const float*)d_in[22];
    const float* b2   = (const float*)d_in[23];
    const float* ln1_g = (const float*)d_in[24];
    const float* ln1_b = (const float*)d_in[25];
    const float* ln2_g = (const float*)d_in[26];
    const float* ln2_b = (const float*)d_in[27];
    const float* ln3_g = (const float*)d_in[28];
    const float* ln3_b = (const float*)d_in[29];
    const float* w_out = (const float*)d_in[30];
    const float* b_out = (const float*)d_in[31];

    void* pv;
    cudaGetSymbolAddress(&pv, g_x);    float* p_gx   = (float*)pv;
    cudaGetSymbolAddress(&pv, g_qkv);  float* p_qkv  = (float*)pv;
    cudaGetSymbolAddress(&pv, g_attn); float* p_attn = (float*)pv;
    cudaGetSymbolAddress(&pv, g_hbuf); float* p_hbuf = (float*)pv;
    cudaGetSymbolAddress(&pv, g_part); float* p_part = (float*)pv;

    const size_t DSQ = (size_t)DD * DD;
    const size_t CACHE_L = (size_t)BB * HH * TPAST * HDIM;

    init_x<<<64, 256>>>(x);

    for (int l = 0; l < 3; l++) {
        const size_t mm = (size_t)l * DSQ;
        const size_t vv = (size_t)l * DD;

        // ---- self-attention ----
        W3 wqkv = {{wq_s + mm, wk_s + mm, wv_s + mm}};
        gemm2<<<dim3(16, 4, 3), 256>>>(p_gx, wqkv, p_part, DD, DD, 64);
        R3 r1 = {{bq_s + vv, bk_s + vv, bv_s + vv},
                 {p_qkv, p_qkv + BB * DD, p_qkv + 2 * BB * DD}};
        reduce_bias<<<dim3(16, 1, 3), 256>>>(p_part, r1, DD, 16, 0);
        attn_part<<<dim3(16, 16, 4), 256>>>(kcache + l * CACHE_L, vcache + l * CACHE_L);
        attn_merge<<<256, 64>>>();
        W3 wos = {{wo_s + mm, 0, 0}};
        gemm2<<<dim3(32, 4, 1), 256>>>(p_attn, wos, p_part, DD, DD, 32);
        reduce_ln<<<16, 1024>>>(p_part, 32, bo_s + vv, ln1_g + vv, ln1_b + vv);

        // ---- cross-attention (folded) ----
        W3 wqc = {{wq_c + mm, 0, 0}};
        gemm2<<<dim3(32, 4, 1), 256>>>(p_gx, wqc, p_part, DD, DD, 32);
        reduce_qc<<<16, 1024>>>(p_part, 32, bq_c + vv, bk_c + vv);
        fold_g<<<dim3(16, 16), 256>>>(wk_c + mm);
        cross_scores<<<dim3(16, 16), 256>>>(enc);
        softmax_sc<<<256, 256>>>();
        cross_ctx<<<dim3(16, 16), 256>>>(enc);
        vproj2<<<dim3(32, 4), 256>>>(wv_c + mm, p_part, 32);
        R3 r2 = {{bv_c + vv, 0, 0}, {p_attn, 0, 0}};
        reduce_bias<<<dim3(16, 1, 1), 256>>>(p_part, r2, DD, 32, 0);
        W3 woc = {{wo_c + mm, 0, 0}};
        gemm2<<<dim3(32, 4, 1), 256>>>(p_attn, woc, p_part, DD, DD, 32);
        reduce_ln<<<16, 1024>>>(p_part, 32, bo_c + vv, ln2_g + vv, ln2_b + vv);

        // ---- FFN ----
        W3 ww1 = {{w1 + (size_t)l * DD * FFD, 0, 0}};
        gemm2<<<dim3(8, 16, 1), 256>>>(p_gx, ww1, p_part, FFD, DD, 128);
        R3 r3 = {{b1 + (size_t)l * FFD, 0, 0}, {p_hbuf, 0, 0}};
        reduce_bias<<<dim3(64, 1, 1), 256>>>(p_part, r3, FFD, 8, 1);
        W3 ww2 = {{w2 + (size_t)l * FFD * DD, 0, 0}};
        gemm2<<<dim3(32, 4, 1), 256>>>(p_hbuf, ww2, p_part, DD, FFD, 128);
        reduce_ln<<<16, 1024>>>(p_part, 32, b2 + vv, ln3_g + vv, ln3_b + vv);
    }

    final_logits<<<dim3(16, VOUT), 256>>>(w_out, b_out, (float*)d_out);
}

// round 11
// speedup vs baseline: 1.1883x; 1.1883x over previous
#include <cuda_runtime.h>

#define BB 16
#define DD 1024
#define HH 16
#define HDIM 64
#define TPAST 1023
#define SENC 1024
#define FFD 4096
#define ASCALE 0.125f
#define LN_EPS 1e-5f
#define VOUT 20

// ------------------------- device scratch (static, no allocation) ----------
__device__ float g_x[BB * DD];              // residual stream
__device__ float g_qkv[3 * BB * DD];        // q | k_new | v_new
__device__ float g_attn[BB * DD];           // attn output / proj input
__device__ float g_qc[BB * DD];             // cross-attn query
__device__ float g_qb[BB * HH];             // q . bk per head
__device__ float g_fold[BB * DD * HH];      // folded K direction [b][e][h]
__device__ float g_sc[BB * HH * SENC];      // cross scores -> probs in place
__device__ float g_ctx[BB * HH * DD];       // cross context [b][h][e]
__device__ float g_hbuf[BB * FFD];          // FFN hidden
__device__ float g_part[4194304];           // k-split GEMM partials (16 MB)

struct W3 { const float* w[3]; };
struct R3 { const float* bias[3]; float* out[3]; };

// ------------------------- init: copy input x -> g_x -----------------------
__global__ void __launch_bounds__(256) init_x(const float* __restrict__ x) {
    int i = blockIdx.x * 256 + threadIdx.x;
    if (i < BB * DD) g_x[i] = x[i];
}

// ------------------------- k-split GEMM v3: float4 weights -----------------
// grid (KS, N/1024, nmats), block 256. Thread owns 4 consecutive n-cols.
__global__ void __launch_bounds__(256) gemm3(const float* __restrict__ x, W3 mats,
                                             float* __restrict__ part,
                                             int N, int K, int kc) {
    __shared__ float sx[1024];                 // up to 16 x 64
    const int k0 = blockIdx.x * kc;
    const float* __restrict__ W = mats.w[blockIdx.z];
    const int tid = threadIdx.x;
    for (int i = tid; i < BB * kc; i += 256) {
        int b = i / kc, kk = i - b * kc;
        sx[i] = x[(size_t)b * K + k0 + kk];
    }
    __syncthreads();
    const int n = blockIdx.y * 1024 + tid * 4;
    float acc[BB][4];
#pragma unroll
    for (int b = 0; b < BB; b++) { acc[b][0] = acc[b][1] = acc[b][2] = acc[b][3] = 0.f; }
#pragma unroll 8
    for (int kk = 0; kk < kc; kk++) {
        float4 w = *(const float4*)(W + (size_t)(k0 + kk) * N + n);
#pragma unroll
        for (int b = 0; b < BB; b++) {
            float xv = sx[b * kc + kk];
            acc[b][0] = fmaf(xv, w.x, acc[b][0]);
            acc[b][1] = fmaf(xv, w.y, acc[b][1]);
            acc[b][2] = fmaf(xv, w.z, acc[b][2]);
            acc[b][3] = fmaf(xv, w.w, acc[b][3]);
        }
    }
    float* pb = part + (size_t)(blockIdx.z * gridDim.x + blockIdx.x) * BB * N;
#pragma unroll
    for (int b = 0; b < BB; b++)
        *(float4*)(pb + (size_t)b * N + n) =
            make_float4(acc[b][0], acc[b][1], acc[b][2], acc[b][3]);
}

// ---------------- folded V projection v3 (float4, per-head K) --------------
// grid (64, 1), block 256, kc=16. Thread's 4 cols share head h = tid>>4.
__global__ void __launch_bounds__(256) vproj3(const float* __restrict__ W,
                                              float* __restrict__ part) {
    __shared__ float sx[BB * HH * 16];         // [b][h][kk] = 16KB
    const int kc = 16;
    const int k0 = blockIdx.x * kc;
    const int tid = threadIdx.x;
    for (int i = tid; i < BB * HH * kc; i += 256) {
        int b = i >> 8, r = i & 255;
        int h = r >> 4, kk = r & 15;
        sx[i] = g_ctx[((size_t)(b * HH + h)) * DD + k0 + kk];
    }
    __syncthreads();
    const int n = tid * 4;
    const int h = tid >> 4;
    float acc[BB][4];
#pragma unroll
    for (int b = 0; b < BB; b++) { acc[b][0] = acc[b][1] = acc[b][2] = acc[b][3] = 0.f; }
#pragma unroll 8
    for (int kk = 0; kk < kc; kk++) {
        float4 w = *(const float4*)(W + (size_t)(k0 + kk) * DD + n);
#pragma unroll
        for (int b = 0; b < BB; b++) {
            float xv = sx[(b * HH + h) * kc + kk];
            acc[b][0] = fmaf(xv, w.x, acc[b][0]);
            acc[b][1] = fmaf(xv, w.y, acc[b][1]);
            acc[b][2] = fmaf(xv, w.z, acc[b][2]);
            acc[b][3] = fmaf(xv, w.w, acc[b][3]);
        }
    }
    float* pb = part + (size_t)blockIdx.x * BB * DD;
#pragma unroll
    for (int b = 0; b < BB; b++)
        *(float4*)(pb + (size_t)b * DD + n) =
            make_float4(acc[b][0], acc[b][1], acc[b][2], acc[b][3]);
}

// ------------------------- reduce partials + bias (+relu) ------------------
__global__ void __launch_bounds__(256) reduce_bias(const float* __restrict__ part, R3 p,
                                                   int N, int KS, int relu) {
    const int z = blockIdx.z;
    const float* pp = part + (size_t)z * KS * BB * N;
    int idx = (blockIdx.x * 256 + threadIdx.x) * 4;
    int b = idx / N, n = idx - b * N;
    float4 a = make_float4(0.f, 0.f, 0.f, 0.f);
#pragma unroll 8
    for (int ks = 0; ks < KS; ks++) {
        float4 v = *(const float4*)(pp + ((size_t)ks * BB + b) * N + n);
        a.x += v.x; a.y += v.y; a.z += v.z; a.w += v.w;
    }
    float4 bi = *(const float4*)(p.bias[z] + n);
    a.x += bi.x; a.y += bi.y; a.z += bi.z; a.w += bi.w;
    if (relu) {
        a.x = fmaxf(a.x, 0.f); a.y = fmaxf(a.y, 0.f);
        a.z = fmaxf(a.z, 0.f); a.w = fmaxf(a.w, 0.f);
    }
    *(float4*)(p.out[z] + (size_t)b * N + n) = a;
}

// ---------------- reduce + bias + residual + LayerNorm -> g_x --------------
__global__ void __launch_bounds__(1024) reduce_ln(const float* __restrict__ part, int KS,
                                                  const float* __restrict__ bias,
                                                  const float* __restrict__ gam,
                                                  const float* __restrict__ bet) {
    const int b = blockIdx.x, n = threadIdx.x;
    float v = 0.f;
#pragma unroll 8
    for (int ks = 0; ks < KS; ks++) v += part[((size_t)ks * BB + b) * DD + n];
    v += bias[n] + g_x[b * DD + n];
    float s = v, q = v * v;
#pragma unroll
    for (int o = 16; o; o >>= 1) {
        s += __shfl_xor_sync(0xffffffffu, s, o);
        q += __shfl_xor_sync(0xffffffffu, q, o);
    }
    __shared__ float s1[32], s2[32], mv[2];
    int w = n >> 5, ln = n & 31;
    if (ln == 0) { s1[w] = s; s2[w] = q; }
    __syncthreads();
    if (w == 0) {
        float a = s1[ln], c = s2[ln];
#pragma unroll
        for (int o = 16; o; o >>= 1) {
            a += __shfl_xor_sync(0xffffffffu, a, o);
            c += __shfl_xor_sync(0xffffffffu, c, o);
        }
        if (ln == 0) {
            float mean = a * (1.f / DD);
            mv[0] = mean;
            mv[1] = rsqrtf(c * (1.f / DD) - mean * mean + LN_EPS);
        }
    }
    __syncthreads();
    g_x[b * DD + n] = (v - mv[0]) * mv[1] * gam[n] + bet[n];
}

// ---------------- reduce cross q + per-head q.bk ---------------------------
__global__ void __launch_bounds__(1024) reduce_qc(const float* __restrict__ part, int KS,
                                                  const float* __restrict__ bias,
                                                  const float* __restrict__ bk) {
    const int b = blockIdx.x, n = threadIdx.x;
    float v = 0.f;
#pragma unroll 8
    for (int ks = 0; ks < KS; ks++) v += part[((size_t)ks * BB + b) * DD + n];
    v += bias[n];
    g_qc[b * DD + n] = v;
    float pb = v * bk[n];
#pragma unroll
    for (int o = 16; o; o >>= 1) pb += __shfl_xor_sync(0xffffffffu, pb, o);
    __shared__ float sw[32];
    if ((n & 31) == 0) sw[n >> 5] = pb;
    __syncthreads();
    if (n < HH) g_qb[b * HH + n] = sw[2 * n] + sw[2 * n + 1];
}

// ---------------- self-attention v2: one block per (b,h) -------------------
// Phase 1: thread-per-t register dot (no shuffles). Phase 2: coalesced V sweep.
__global__ void __launch_bounds__(256) attn2(const float* __restrict__ kcache,
                                             const float* __restrict__ vcache) {
    const int b = blockIdx.x, h = blockIdx.y;
    const int tid = threadIdx.x, warp = tid >> 5, lane = tid & 31;
    __shared__ float sq[HDIM];
    __shared__ float sp[1024];
    __shared__ float red[8];
    __shared__ float sa[8][64];
    __shared__ float smax, ssum;
    if (tid < 16)
        ((float4*)sq)[tid] = ((const float4*)(g_qkv + b * DD + h * HDIM))[tid];
    __syncthreads();
    const size_t base = (size_t)(b * HH + h) * TPAST * HDIM;
    const float* knew = g_qkv + BB * DD + b * DD + h * HDIM;
    const float* vnew = g_qkv + 2 * BB * DD + b * DD + h * HDIM;
    float p[4];
#pragma unroll
    for (int j = 0; j < 4; j++) {
        int t = tid + j * 256;
        const float* kr = (t < TPAST) ? (kcache + base + (size_t)t * HDIM) : knew;
        float d0 = 0.f, d1 = 0.f, d2 = 0.f, d3 = 0.f;
#pragma unroll
        for (int i = 0; i < 16; i++) {
            float4 k4 = ((const float4*)kr)[i];
            float4 q4 = ((const float4*)sq)[i];
            d0 = fmaf(k4.x, q4.x, d0);
            d1 = fmaf(k4.y, q4.y, d1);
            d2 = fmaf(k4.z, q4.z, d2);
            d3 = fmaf(k4.w, q4.w, d3);
        }
        p[j] = ((d0 + d1) + (d2 + d3)) * ASCALE;
    }
    // block max
    float m = fmaxf(fmaxf(p[0], p[1]), fmaxf(p[2], p[3]));
#pragma unroll
    for (int o = 16; o; o >>= 1) m = fmaxf(m, __shfl_xor_sync(0xffffffffu, m, o));
    if (lane == 0) red[warp] = m;
    __syncthreads();
    if (tid == 0) {
        float M = red[0];
#pragma unroll
        for (int w = 1; w < 8; w++) M = fmaxf(M, red[w]);
        smax = M;
    }
    __syncthreads();
    const float M = smax;
    float l = 0.f;
#pragma unroll
    for (int j = 0; j < 4; j++) {
        float e = __expf(p[j] - M);
        sp[tid + j * 256] = e;
        l += e;
    }
#pragma unroll
    for (int o = 16; o; o >>= 1) l += __shfl_xor_sync(0xffffffffu, l, o);
    __syncthreads();                 // sp visible; red free for reuse
    if (lane == 0) red[warp] = l;
    __syncthreads();
    if (tid == 0) {
        float S = red[0];
#pragma unroll
        for (int w = 1; w < 8; w++) S += red[w];
        ssum = S;
    }
    // Phase 2: V accumulation, warp w owns t in [w*128, w*128+128)
    float a0 = 0.f, a1 = 0.f;
    const int tb = warp * 128;
#pragma unroll 4
    for (int tt = 0; tt < 128; tt++) {
        int t = tb + tt;
        const float* vr = (t < TPAST) ? (vcache + base + (size_t)t * HDIM) : vnew;
        float2 v = *(const float2*)(vr + lane * 2);
        float e = sp[t];
        a0 = fmaf(e, v.x, a0);
        a1 = fmaf(e, v.y, a1);
    }
    sa[warp][lane * 2] = a0;
    sa[warp][lane * 2 + 1] = a1;
    __syncthreads();
    if (tid < 64) {
        float o = 0.f;
#pragma unroll
        for (int w = 0; w < 8; w++) o += sa[w][tid];
        g_attn[b * DD + h * HDIM + tid] = o / ssum;
    }
}

// ---------------- fold K projection v2: 4 batches share one wk scan --------
// grid (16 e-tiles, 4 b-groups), block 256 (8 warps); warp handles 8 e-rows.
__global__ void __launch_bounds__(256) fold_g4(const float* __restrict__ wk) {
    const int bg = blockIdx.y * 4;
    const int e0 = blockIdx.x * 64;
    const int tid = threadIdx.x, warp = tid >> 5, lane = tid & 31;
    __shared__ float sq[4][DD];
    for (int i = tid; i < 4 * DD; i += 256)
        sq[i >> 10][i & 1023] = g_qc[(bg + (i >> 10)) * DD + (i & 1023)];
    __syncthreads();
#pragma unroll
    for (int j = 0; j < 8; j++) {
        int e = e0 + warp * 8 + j;
        const float* wr = wk + (size_t)e * DD;
        float gv0 = 0.f, gv1 = 0.f, gv2 = 0.f, gv3 = 0.f;
#pragma unroll
        for (int h = 0; h < HH; h++) {
            float w0 = wr[h * 64 + lane], w1 = wr[h * 64 + 32 + lane];
            float s0 = fmaf(w0, sq[0][h * 64 + lane], w1 * sq[0][h * 64 + 32 + lane]);
            float s1 = fmaf(w0, sq[1][h * 64 + lane], w1 * sq[1][h * 64 + 32 + lane]);
            float s2 = fmaf(w0, sq[2][h * 64 + lane], w1 * sq[2][h * 64 + 32 + lane]);
            float s3 = fmaf(w0, sq[3][h * 64 + lane], w1 * sq[3][h * 64 + 32 + lane]);
#pragma unroll
            for (int o = 16; o; o >>= 1) {
                s0 += __shfl_xor_sync(0xffffffffu, s0, o);
                s1 += __shfl_xor_sync(0xffffffffu, s1, o);
                s2 += __shfl_xor_sync(0xffffffffu, s2, o);
                s3 += __shfl_xor_sync(0xffffffffu, s3, o);
            }
            if (lane == h) { gv0 = s0; gv1 = s1; gv2 = s2; gv3 = s3; }
        }
        if (lane < HH) {
            g_fold[((size_t)((bg + 0) * DD + e)) * HH + lane] = gv0;
            g_fold[((size_t)((bg + 1) * DD + e)) * HH + lane] = gv1;
            g_fold[((size_t)((bg + 2) * DD + e)) * HH + lane] = gv2;
            g_fold[((size_t)((bg + 3) * DD + e)) * HH + lane] = gv3;
        }
    }
}

// ---------------- cross scores: enc . g + qb -------------------------------
__global__ void __launch_bounds__(256) cross_scores(const float* __restrict__ enc) {
    const int b = blockIdx.y;
    const int s0 = blockIdx.x * 64;
    const int tid = threadIdx.x;
    const int s_loc = tid >> 2, hg = tid & 3;
    __shared__ float se[64][68];
    float acc[4] = {0.f, 0.f, 0.f, 0.f};
    for (int ec = 0; ec < 16; ec++) {
        int e0 = ec * 64;
        for (int i = tid; i < 1024; i += 256) {
            int r = i >> 4, c4 = (i & 15) * 4;
            float4 v = *(const float4*)(enc + ((size_t)(b * SENC + s0 + r)) * DD + e0 + c4);
            *(float4*)&se[r][c4] = v;
        }
        __syncthreads();
        const float* gf = g_fold + ((size_t)b * DD + e0) * HH + hg * 4;
#pragma unroll 4
        for (int e = 0; e < 64; e++) {
            float4 g4 = *(const float4*)(gf + e * HH);
            float ev = se[s_loc][e];
            acc[0] = fmaf(ev, g4.x, acc[0]);
            acc[1] = fmaf(ev, g4.y, acc[1]);
            acc[2] = fmaf(ev, g4.z, acc[2]);
            acc[3] = fmaf(ev, g4.w, acc[3]);
        }
        __syncthreads();
    }
    int s = s0 + s_loc;
#pragma unroll
    for (int i = 0; i < 4; i++) {
        int h = hg * 4 + i;
        g_sc[((size_t)(b * HH + h)) * SENC + s] = (acc[i] + g_qb[b * HH + h]) * ASCALE;
    }
}

// ---------------- softmax over s (in place) --------------------------------
__global__ void __launch_bounds__(256) softmax_sc() {
    const int bh = blockIdx.x, tid = threadIdx.x;
    float* row = g_sc + (size_t)bh * SENC;
    float4 v = *(float4*)(row + tid * 4);
    float m = fmaxf(fmaxf(v.x, v.y), fmaxf(v.z, v.w));
#pragma unroll
    for (int o = 16; o; o >>= 1) m = fmaxf(m, __shfl_xor_sync(0xffffffffu, m, o));
    __shared__ float sh[8], sh2[8];
    int w = tid >> 5, ln = tid & 31;
    if (ln == 0) sh[w] = m;
    __syncthreads();
    float M = sh[0];
#pragma unroll
    for (int i = 1; i < 8; i++) M = fmaxf(M, sh[i]);
    float e0 = __expf(v.x - M), e1 = __expf(v.y - M);
    float e2 = __expf(v.z - M), e3 = __expf(v.w - M);
    float s = e0 + e1 + e2 + e3;
#pragma unroll
    for (int o = 16; o; o >>= 1) s += __shfl_xor_sync(0xffffffffu, s, o);
    if (ln == 0) sh2[w] = s;
    __syncthreads();
    float S = sh2[0];
#pragma unroll
    for (int i = 1; i < 8; i++) S += sh2[i];
    float r = 1.f / S;
    *(float4*)(row + tid * 4) = make_float4(e0 * r, e1 * r, e2 * r, e3 * r);
}

// ---------------- cross context: ctx[b][h][e] = sum_s p * enc --------------
__global__ void __launch_bounds__(256) cross_ctx(const float* __restrict__ enc) {
    const int b = blockIdx.y;
    const int e0 = blockIdx.x * 64;
    const int tid = threadIdx.x;
    const int e_loc = tid & 63, hg = tid >> 6;
    __shared__ float sp[16][65];
    float acc[4] = {0.f, 0.f, 0.f, 0.f};
    for (int sc = 0; sc < 16; sc++) {
        int s0 = sc * 64;
        for (int i = tid; i < 1024; i += 256) {
            int h = i >> 6, sl = i & 63;
            sp[h][sl] = g_sc[((size_t)(b * HH + h)) * SENC + s0 + sl];
        }
        __syncthreads();
        const float* ep = enc + ((size_t)(b * SENC + s0)) * DD + e0 + e_loc;
#pragma unroll 4
        for (int sl = 0; sl < 64; sl++) {
            float ev = ep[(size_t)sl * DD];
#pragma unroll
            for (int i = 0; i < 4; i++) acc[i] = fmaf(ev, sp[hg * 4 + i][sl], acc[i]);
        }
        __syncthreads();
    }
#pragma unroll
    for (int i = 0; i < 4; i++)
        g_ctx[((size_t)(b * HH + hg * 4 + i)) * DD + e0 + e_loc] = acc[i];
}

// ---------------- final logits ---------------------------------------------
__global__ void __launch_bounds__(256) final_logits(const float* __restrict__ wout,
                                                    const float* __restrict__ bout,
                                                    float* __restrict__ out) {
    const int b = blockIdx.x, v = blockIdx.y, tid = threadIdx.x;
    float s = 0.f;
    for (int d = tid; d < DD; d += 256) s = fmaf(g_x[b * DD + d], wout[d * VOUT + v], s);
#pragma unroll
    for (int o = 16; o; o >>= 1) s += __shfl_xor_sync(0xffffffffu, s, o);
    __shared__ float sw[8];
    if ((tid & 31) == 0) sw[tid >> 5] = s;
    __syncthreads();
    if (tid == 0) {
        float t = sw[0];
#pragma unroll
        for (int i = 1; i < 8; i++) t += sw[i];
        out[b * VOUT + v] = t + bout[v];
    }
}

// ===========================================================================
extern "C" void kernel_launch(void* const* d_in, const int* in_sizes, int n_in,
                              void* d_out, int out_size) {
    const float* x      = (const float*)d_in[0];
    const float* enc    = (const float*)d_in[1];
    const float* kcache = (const float*)d_in[2];
    const float* vcache = (const float*)d_in[3];
    const float* wq_s = (const float*)d_in[4];
    const float* bq_s = (const float*)d_in[5];
    const float* wk_s = (const float*)d_in[6];
    const float* bk_s = (const float*)d_in[7];
    const float* wv_s = (const float*)d_in[8];
    const float* bv_s = (const float*)d_in[9];
    const float* wo_s = (const float*)d_in[10];
    const float* bo_s = (const float*)d_in[11];
    const float* wq_c = (const float*)d_in[12];
    const float* bq_c = (const float*)d_in[13];
    const float* wk_c = (const float*)d_in[14];
    const float* bk_c = (const float*)d_in[15];
    const float* wv_c = (const float*)d_in[16];
    const float* bv_c = (const float*)d_in[17];
    const float* wo_c = (const float*)d_in[18];
    const float* bo_c = (const float*)d_in[19];
    const float* w1   = (const float*)d_in[20];
    const float* b1   = (const float*)d_in[21];
    const float* w2   = (const float*)d_in[22];
    const float* b2   = (const float*)d_in[23];
    const float* ln1_g = (const float*)d_in[24];
    const float* ln1_b = (const float*)d_in[25];
    const float* ln2_g = (const float*)d_in[26];
    const float* ln2_b = (const float*)d_in[27];
    const float* ln3_g = (const float*)d_in[28];
    const float* ln3_b = (const float*)d_in[29];
    const float* w_out = (const float*)d_in[30];
    const float* b_out = (const float*)d_in[31];

    void* pv;
    cudaGetSymbolAddress(&pv, g_x);    float* p_gx   = (float*)pv;
    cudaGetSymbolAddress(&pv, g_qkv);  float* p_qkv  = (float*)pv;
    cudaGetSymbolAddress(&pv, g_attn); float* p_attn = (float*)pv;
    cudaGetSymbolAddress(&pv, g_hbuf); float* p_hbuf = (float*)pv;
    cudaGetSymbolAddress(&pv, g_part); float* p_part = (float*)pv;

    const size_t DSQ = (size_t)DD * DD;
    const size_t CACHE_L = (size_t)BB * HH * TPAST * HDIM;

    init_x<<<64, 256>>>(x);

    for (int l = 0; l < 3; l++) {
        const size_t mm = (size_t)l * DSQ;
        const size_t vv = (size_t)l * DD;

        // ---- self-attention ----
        W3 wqkv = {{wq_s + mm, wk_s + mm, wv_s + mm}};
        gemm3<<<dim3(64, 1, 3), 256>>>(p_gx, wqkv, p_part, DD, DD, 16);
        R3 r1 = {{bq_s + vv, bk_s + vv, bv_s + vv},
                 {p_qkv, p_qkv + BB * DD, p_qkv + 2 * BB * DD}};
        reduce_bias<<<dim3(16, 1, 3), 256>>>(p_part, r1, DD, 64, 0);
        attn2<<<dim3(16, 16), 256>>>(kcache + l * CACHE_L, vcache + l * CACHE_L);
        W3 wos = {{wo_s + mm, 0, 0}};
        gemm3<<<dim3(128, 1, 1), 256>>>(p_attn, wos, p_part, DD, DD, 8);
        reduce_ln<<<16, 1024>>>(p_part, 128, bo_s + vv, ln1_g + vv, ln1_b + vv);

        // ---- cross-attention (folded) ----
        W3 wqc = {{wq_c + mm, 0, 0}};
        gemm3<<<dim3(128, 1, 1), 256>>>(p_gx, wqc, p_part, DD, DD, 8);
        reduce_qc<<<16, 1024>>>(p_part, 128, bq_c + vv, bk_c + vv);
        fold_g4<<<dim3(16, 4), 256>>>(wk_c + mm);
        cross_scores<<<dim3(16, 16), 256>>>(enc);
        softmax_sc<<<256, 256>>>();
        cross_ctx<<<dim3(16, 16), 256>>>(enc);
        vproj3<<<64, 256>>>(wv_c + mm, p_part);
        R3 r2 = {{bv_c + vv, 0, 0}, {p_attn, 0, 0}};
        reduce_bias<<<dim3(16, 1, 1), 256>>>(p_part, r2, DD, 64, 0);
        W3 woc = {{wo_c + mm, 0, 0}};
        gemm3<<<dim3(128, 1, 1), 256>>>(p_attn, woc, p_part, DD, DD, 8);
        reduce_ln<<<16, 1024>>>(p_part, 128, bo_c + vv, ln2_g + vv, ln2_b + vv);

        // ---- FFN ----
        W3 ww1 = {{w1 + (size_t)l * DD * FFD, 0, 0}};
        gemm3<<<dim3(32, 4, 1), 256>>>(p_gx, ww1, p_part, FFD, DD, 32);
        R3 r3 = {{b1 + (size_t)l * FFD, 0, 0}, {p_hbuf, 0, 0}};
        reduce_bias<<<dim3(64, 1, 1), 256>>>(p_part, r3, FFD, 32, 1);
        W3 ww2 = {{w2 + (size_t)l * FFD * DD, 0, 0}};
        gemm3<<<dim3(128, 1, 1), 256>>>(p_hbuf, ww2, p_part, DD, FFD, 32);
        reduce_ln<<<16, 1024>>>(p_part, 128, b2 + vv, ln3_g + vv, ln3_b + vv);
    }

    final_logits<<<dim3(16, VOUT), 256>>>(w_out, b_out, (float*)d_out);
}

// round 14
// speedup vs baseline: 1.7427x; 1.4665x over previous
#include <cuda_runtime.h>

#define GRID 148
#define NT 1024
#define BB 16
#define DD 1024
#define HH 16
#define HDIM 64
#define TPAST 1023
#define SENC 1024
#define FFD 4096
#define ASCALE 0.125f
#define LN_EPS 1e-5f
#define VOUT 20

// ------------------------- device scratch (static, no allocation) ----------
__device__ int   g_bar;
__device__ float g_x[BB * DD];
__device__ float g_qkv[3 * BB * DD];
__device__ float g_attn[BB * DD];
__device__ float g_qc[BB * DD];
__device__ float g_qb[BB * HH];
__device__ float g_fold[BB * DD * HH];      // [b][e][h]
__device__ float g_sc[BB * HH * SENC];      // scores half 0 -> probs
__device__ float g_sc2[BB * HH * SENC];     // scores half 1
__device__ float g_ctx[BB * HH * DD];       // ctx half 0
__device__ float g_ctx2[BB * HH * DD];      // ctx half 1
__device__ float g_hbuf[BB * FFD];
__device__ float g_part[2097152];           // 8 MB partials

struct KP {
    const float *x, *enc, *kc, *vc;
    const float *wq_s, *bq_s, *wk_s, *bk_s, *wv_s, *bv_s, *wo_s, *bo_s;
    const float *wq_c, *bq_c, *wk_c, *bk_c, *wv_c, *bv_c, *wo_c, *bo_c;
    const float *w1, *b1, *w2, *b2;
    const float *ln1g, *ln1b, *ln2g, *ln2b, *ln3g, *ln3b;
    const float *wout, *bout;
    float *out;
};

__global__ void reset_bar() { g_bar = 0; }

// grid-wide barrier: release-arrive + acquire-spin (tid 0), CTA bar around it.
#define GSYNC() do {                                                     \
    __syncthreads();                                                     \
    ph++;                                                                \
    if (tid == 0) {                                                      \
        __threadfence();                                                 \
        atomicAdd(&g_bar, 1);                                            \
        while (*((volatile int*)&g_bar) < ph * GRID) { __nanosleep(32); }\
        __threadfence();                                                 \
    }                                                                    \
    __syncthreads();                                                     \
} while (0)

// ---------------- k-split DDxDD GEMM partials (64 tasks, kc=16) ------------
__device__ __forceinline__ void gemmDD(const float* __restrict__ X,
                                       const float* __restrict__ W,
                                       int bx, int tid, float* sm) {
    for (int task = bx; task < 64; task += GRID) {
        const int k0 = task * 16;
        if (tid < 256) sm[tid] = X[(tid >> 4) * DD + k0 + (tid & 15)];
        __syncthreads();
        float acc[16];
#pragma unroll
        for (int b = 0; b < 16; b++) acc[b] = 0.f;
#pragma unroll
        for (int kk = 0; kk < 16; kk++) {
            float w = W[(size_t)(k0 + kk) * DD + tid];
#pragma unroll
            for (int b = 0; b < 16; b++) acc[b] = fmaf(sm[b * 16 + kk], w, acc[b]);
        }
        float* pb = g_part + (size_t)task * BB * DD + tid;
#pragma unroll
        for (int b = 0; b < 16; b++) pb[b * DD] = acc[b];
        __syncthreads();
    }
}

// ---------------- reduce partials + bias + residual + LN -> g_x ------------
__device__ __forceinline__ void ln_red(int KS, const float* __restrict__ bias,
                                       const float* __restrict__ gam,
                                       const float* __restrict__ bet,
                                       int bx, int tid, float* sm) {
    const int lane = tid & 31, warp = tid >> 5;
    for (int task = bx; task < 16; task += GRID) {
        float v = 0.f;
#pragma unroll 8
        for (int ks = 0; ks < KS; ks++) v += g_part[(size_t)(ks * 16 + task) * DD + tid];
        v += bias[tid] + g_x[task * DD + tid];
        float s = v, q = v * v;
#pragma unroll
        for (int o = 16; o; o >>= 1) {
            s += __shfl_xor_sync(0xffffffffu, s, o);
            q += __shfl_xor_sync(0xffffffffu, q, o);
        }
        if (lane == 0) { sm[warp] = s; sm[32 + warp] = q; }
        __syncthreads();
        if (tid < 32) {
            float a = sm[tid], c = sm[32 + tid];
#pragma unroll
            for (int o = 16; o; o >>= 1) {
                a += __shfl_xor_sync(0xffffffffu, a, o);
                c += __shfl_xor_sync(0xffffffffu, c, o);
            }
            if (tid == 0) {
                float mean = a * (1.f / DD);
                sm[64] = mean;
                sm[65] = rsqrtf(c * (1.f / DD) - mean * mean + LN_EPS);
            }
        }
        __syncthreads();
        g_x[task * DD + tid] = (v - sm[64]) * sm[65] * gam[tid] + bet[tid];
        __syncthreads();
    }
}

__global__ void __launch_bounds__(NT, 1) mega(KP P) {
    const int bx = blockIdx.x;
    const int tid = threadIdx.x;
    const int lane = tid & 31, warp = tid >> 5;
    int ph = 0;
    __shared__ float sm[5440];

    // ---- P0: init residual stream ----
    for (int i = bx * NT + tid; i < BB * DD; i += GRID * NT) g_x[i] = P.x[i];
    GSYNC();

    for (int l = 0; l < 3; l++) {
        const size_t mo = (size_t)l * DD * DD;
        const size_t vo = (size_t)l * DD;
        const float* wq = P.wq_s + mo; const float* bq = P.bq_s + vo;
        const float* wk = P.wk_s + mo; const float* bk = P.bk_s + vo;
        const float* wv = P.wv_s + mo; const float* bv = P.bv_s + vo;
        const float* wo = P.wo_s + mo; const float* bo = P.bo_s + vo;
        const float* wqc = P.wq_c + mo; const float* bqc = P.bq_c + vo;
        const float* wkc = P.wk_c + mo; const float* bkc = P.bk_c + vo;
        const float* wvc = P.wv_c + mo; const float* bvc = P.bv_c + vo;
        const float* woc = P.wo_c + mo; const float* boc = P.bo_c + vo;
        const float* w1l = P.w1 + (size_t)l * DD * FFD; const float* b1l = P.b1 + (size_t)l * FFD;
        const float* w2l = P.w2 + (size_t)l * FFD * DD; const float* b2l = P.b2 + vo;
        const float* kcl = P.kc + (size_t)l * BB * HH * TPAST * HDIM;
        const float* vcl = P.vc + (size_t)l * BB * HH * TPAST * HDIM;

        // ---- P1: qkv GEMM partials (96 tasks, kc=32) ----
        for (int task = bx; task < 96; task += GRID) {
            const int mm = task >> 5, ks = task & 31, k0 = ks * 32;
            const float* W = mm == 0 ? wq : (mm == 1 ? wk : wv);
            if (tid < 512) sm[tid] = g_x[(tid >> 5) * DD + k0 + (tid & 31)];
            __syncthreads();
            float acc[16];
#pragma unroll
            for (int b = 0; b < 16; b++) acc[b] = 0.f;
#pragma unroll 8
            for (int kk = 0; kk < 32; kk++) {
                float w = W[(size_t)(k0 + kk) * DD + tid];
#pragma unroll
                for (int b = 0; b < 16; b++) acc[b] = fmaf(sm[b * 32 + kk], w, acc[b]);
            }
            float* pb = g_part + (size_t)task * BB * DD + tid;
#pragma unroll
            for (int b = 0; b < 16; b++) pb[b * DD] = acc[b];
            __syncthreads();
        }
        GSYNC();

        // ---- P2: reduce qkv + bias -> g_qkv ----
        for (int task = bx; task < 48; task += GRID) {
            const int mm = task >> 4, b = task & 15;
            const float* bs = mm == 0 ? bq : (mm == 1 ? bk : bv);
            float v = 0.f;
#pragma unroll 8
            for (int ks = 0; ks < 32; ks++)
                v += g_part[(size_t)((mm * 32 + ks) * 16 + b) * DD + tid];
            g_qkv[mm * BB * DD + b * DD + tid] = v + bs[tid];
        }
        GSYNC();

        // ---- P3: self-attention over KV cache (256 tasks) ----
        {
            float* sq = sm;            // 64
            float* sp = sm + 64;       // 1024
            float* red = sm + 1088;    // 32
            float* sa = sm + 1120;     // 2048
            float* sval = sm + 3168;   // 2
            for (int task = bx; task < 256; task += GRID) {
                const int b = task >> 4, h = task & 15;
                if (tid < 16)
                    ((float4*)sq)[tid] = ((const float4*)(g_qkv + b * DD + h * HDIM))[tid];
                __syncthreads();
                const size_t base = (size_t)(b * HH + h) * TPAST * HDIM;
                const float* kr = (tid < TPAST) ? kcl + base + (size_t)tid * HDIM
                                                : g_qkv + BB * DD + b * DD + h * HDIM;
                float d0 = 0.f, d1 = 0.f, d2 = 0.f, d3 = 0.f;
#pragma unroll
                for (int i = 0; i < 16; i++) {
                    float4 k4 = ((const float4*)kr)[i];
                    float4 q4 = ((const float4*)sq)[i];
                    d0 = fmaf(k4.x, q4.x, d0); d1 = fmaf(k4.y, q4.y, d1);
                    d2 = fmaf(k4.z, q4.z, d2); d3 = fmaf(k4.w, q4.w, d3);
                }
                float p = ((d0 + d1) + (d2 + d3)) * ASCALE;
                float m = p;
#pragma unroll
                for (int o = 16; o; o >>= 1) m = fmaxf(m, __shfl_xor_sync(0xffffffffu, m, o));
                if (lane == 0) red[warp] = m;
                __syncthreads();
                if (tid < 32) {
                    float M = red[tid];
#pragma unroll
                    for (int o = 16; o; o >>= 1) M = fmaxf(M, __shfl_xor_sync(0xffffffffu, M, o));
                    if (tid == 0) sval[0] = M;
                }
                __syncthreads();
                float e = __expf(p - sval[0]);
                sp[tid] = e;
                float s = e;
#pragma unroll
                for (int o = 16; o; o >>= 1) s += __shfl_xor_sync(0xffffffffu, s, o);
                __syncthreads();
                if (lane == 0) red[warp] = s;
                __syncthreads();
                if (tid < 32) {
                    float S = red[tid];
#pragma unroll
                    for (int o = 16; o; o >>= 1) S += __shfl_xor_sync(0xffffffffu, S, o);
                    if (tid == 0) sval[1] = S;
                }
                __syncthreads();
                float a0 = 0.f, a1 = 0.f;
#pragma unroll 4
                for (int tt = 0; tt < 32; tt++) {
                    int t = warp * 32 + tt;
                    const float* vr = (t < TPAST) ? vcl + base + (size_t)t * HDIM
                                                  : g_qkv + 2 * BB * DD + b * DD + h * HDIM;
                    float2 v = *(const float2*)(vr + lane * 2);
                    float e2 = sp[t];
                    a0 = fmaf(e2, v.x, a0); a1 = fmaf(e2, v.y, a1);
                }
                sa[warp * 64 + lane * 2] = a0;
                sa[warp * 64 + lane * 2 + 1] = a1;
                __syncthreads();
                if (tid < 64) {
                    float o = 0.f;
#pragma unroll
                    for (int w = 0; w < 32; w++) o += sa[w * 64 + tid];
                    g_attn[b * DD + h * HDIM + tid] = o / sval[1];
                }
                __syncthreads();
            }
        }
        GSYNC();

        // ---- P4/P5: wo GEMM + reduce/LN1 ----
        gemmDD(g_attn, wo, bx, tid, sm);
        GSYNC();
        ln_red(64, bo, P.ln1g + vo, P.ln1b + vo, bx, tid, sm);
        GSYNC();

        // ---- P6/P7: cross q GEMM + reduce (g_qc, g_qb) ----
        gemmDD(g_x, wqc, bx, tid, sm);
        GSYNC();
        for (int task = bx; task < 16; task += GRID) {
            float v = 0.f;
#pragma unroll 8
            for (int ks = 0; ks < 64; ks++)
                v += g_part[(size_t)(ks * 16 + task) * DD + tid];
            v += bqc[tid];
            g_qc[task * DD + tid] = v;
            float pb = v * bkc[tid];
#pragma unroll
            for (int o = 16; o; o >>= 1) pb += __shfl_xor_sync(0xffffffffu, pb, o);
            if (lane == 0) sm[warp] = pb;
            __syncthreads();
            if (tid < 16) g_qb[task * HH + tid] = sm[2 * tid] + sm[2 * tid + 1];
            __syncthreads();
        }
        GSYNC();

        // ---- P8: fold K projection -> g_fold (64 tasks) ----
        for (int task = bx; task < 64; task += GRID) {
            const int et = task >> 2, bg = (task & 3) * 4, e0 = et * 64;
            for (int i = tid; i < 4 * DD; i += NT)
                sm[i] = g_qc[(bg + (i >> 10)) * DD + (i & 1023)];
            __syncthreads();
#pragma unroll
            for (int j = 0; j < 2; j++) {
                int e = e0 + warp * 2 + j;
                const float* wr = wkc + (size_t)e * DD;
                float gv0 = 0.f, gv1 = 0.f, gv2 = 0.f, gv3 = 0.f;
#pragma unroll
                for (int h = 0; h < HH; h++) {
                    float w0 = wr[h * 64 + lane], w1 = wr[h * 64 + 32 + lane];
                    float s0 = fmaf(w0, sm[h * 64 + lane], w1 * sm[h * 64 + 32 + lane]);
                    float s1 = fmaf(w0, sm[1024 + h * 64 + lane], w1 * sm[1024 + h * 64 + 32 + lane]);
                    float s2 = fmaf(w0, sm[2048 + h * 64 + lane], w1 * sm[2048 + h * 64 + 32 + lane]);
                    float s3 = fmaf(w0, sm[3072 + h * 64 + lane], w1 * sm[3072 + h * 64 + 32 + lane]);
#pragma unroll
                    for (int o = 16; o; o >>= 1) {
                        s0 += __shfl_xor_sync(0xffffffffu, s0, o);
                        s1 += __shfl_xor_sync(0xffffffffu, s1, o);
                        s2 += __shfl_xor_sync(0xffffffffu, s2, o);
                        s3 += __shfl_xor_sync(0xffffffffu, s3, o);
                    }
                    if (lane == h) { gv0 = s0; gv1 = s1; gv2 = s2; gv3 = s3; }
                }
                if (lane < HH) {
                    g_fold[((size_t)((bg + 0) * DD + e)) * HH + lane] = gv0;
                    g_fold[((size_t)((bg + 1) * DD + e)) * HH + lane] = gv1;
                    g_fold[((size_t)((bg + 2) * DD + e)) * HH + lane] = gv2;
                    g_fold[((size_t)((bg + 3) * DD + e)) * HH + lane] = gv3;
                }
            }
            __syncthreads();
        }
        GSYNC();

        // ---- P9: cross scores, e-halved (128 tasks) ----
        {
            float* se = sm;            // 256 x 20 = 5120
            float* gfs = sm + 5120;    // 256
            const int s_loc = tid >> 2, hg = tid & 3;
            for (int task = bx; task < 128; task += GRID) {
                const int eh = task >> 6, st = (task >> 4) & 3, b = task & 15;
                const int s0 = st * 256;
                float acc[4] = {0.f, 0.f, 0.f, 0.f};
                for (int ec = 0; ec < 32; ec++) {
                    const int e0 = eh * 512 + ec * 16;
                    {
                        int sr = tid >> 2, c4 = (tid & 3) * 4;
                        *(float4*)(se + sr * 20 + c4) =
                            *(const float4*)(P.enc + ((size_t)(b * SENC + s0 + sr)) * DD + e0 + c4);
                    }
                    if (tid < 256)
                        gfs[tid] = g_fold[((size_t)(b * DD + e0 + (tid >> 4))) * HH + (tid & 15)];
                    __syncthreads();
#pragma unroll
                    for (int e = 0; e < 16; e++) {
                        float ev = se[s_loc * 20 + e];
                        float4 g4 = ((float4*)gfs)[e * 4 + hg];
                        acc[0] = fmaf(ev, g4.x, acc[0]);
                        acc[1] = fmaf(ev, g4.y, acc[1]);
                        acc[2] = fmaf(ev, g4.z, acc[2]);
                        acc[3] = fmaf(ev, g4.w, acc[3]);
                    }
                    __syncthreads();
                }
                float* dst = eh ? g_sc2 : g_sc;
#pragma unroll
                for (int i = 0; i < 4; i++)
                    dst[((size_t)(b * HH + hg * 4 + i)) * SENC + s0 + s_loc] = acc[i];
            }
        }
        GSYNC();

        // ---- P10: softmax (adds halves + qb, scales) (256 tasks) ----
        for (int task = bx; task < 256; task += GRID) {
            const int b = task >> 4, h = task & 15;
            const size_t row = (size_t)task * SENC;
            float v = (g_sc[row + tid] + g_sc2[row + tid] + g_qb[b * HH + h]) * ASCALE;
            float m = v;
#pragma unroll
            for (int o = 16; o; o >>= 1) m = fmaxf(m, __shfl_xor_sync(0xffffffffu, m, o));
            if (lane == 0) sm[warp] = m;
            __syncthreads();
            if (tid < 32) {
                float M = sm[tid];
#pragma unroll
                for (int o = 16; o; o >>= 1) M = fmaxf(M, __shfl_xor_sync(0xffffffffu, M, o));
                if (tid == 0) sm[64] = M;
            }
            __syncthreads();
            float e = __expf(v - sm[64]);
            float s = e;
#pragma unroll
            for (int o = 16; o; o >>= 1) s += __shfl_xor_sync(0xffffffffu, s, o);
            __syncthreads();
            if (lane == 0) sm[warp] = s;
            __syncthreads();
            if (tid < 32) {
                float S = sm[tid];
#pragma unroll
                for (int o = 16; o; o >>= 1) S += __shfl_xor_sync(0xffffffffu, S, o);
                if (tid == 0) sm[65] = S;
            }
            __syncthreads();
            g_sc[row + tid] = e / sm[65];
            __syncthreads();
        }
        GSYNC();

        // ---- P11: cross context, s-halved (128 tasks) ----
        {
            float* spT = sm;           // 256
            float* se2 = sm + 256;     // 16 x 260 = 4160
            const int e_loc = tid >> 2, hg = tid & 3;
            for (int task = bx; task < 128; task += GRID) {
                const int sh = task >> 6, et = (task >> 4) & 3, b = task & 15;
                const int e0 = et * 256;
                float acc[4] = {0.f, 0.f, 0.f, 0.f};
                for (int sc = 0; sc < 32; sc++) {
                    const int soff = sh * 512 + sc * 16;
                    {
                        int r = tid >> 6, c4 = (tid & 63) * 4;
                        *(float4*)(se2 + r * 260 + c4) =
                            *(const float4*)(P.enc + ((size_t)(b * SENC + soff + r)) * DD + e0 + c4);
                    }
                    if (tid < 256)
                        spT[(tid >> 4) * 16 + (tid & 15)] =
                            g_sc[((size_t)(b * HH + (tid & 15))) * SENC + soff + (tid >> 4)];
                    __syncthreads();
#pragma unroll
                    for (int sl = 0; sl < 16; sl++) {
                        float ev = se2[sl * 260 + e_loc];
                        float4 p4 = ((float4*)spT)[sl * 4 + hg];
                        acc[0] = fmaf(ev, p4.x, acc[0]);
                        acc[1] = fmaf(ev, p4.y, acc[1]);
                        acc[2] = fmaf(ev, p4.z, acc[2]);
                        acc[3] = fmaf(ev, p4.w, acc[3]);
                    }
                    __syncthreads();
                }
                float* dst = sh ? g_ctx2 : g_ctx;
#pragma unroll
                for (int i = 0; i < 4; i++)
                    dst[((size_t)(b * HH + hg * 4 + i)) * DD + e0 + e_loc] = acc[i];
            }
        }
        GSYNC();

        // ---- P12: folded V projection partials (64 tasks) ----
        for (int task = bx; task < 64; task += GRID) {
            const int k0 = task * 16;
            for (int i = tid; i < 4096; i += NT) {
                int b = i >> 8, h = (i >> 4) & 15, kk = i & 15;
                size_t ci = ((size_t)(b * HH + h)) * DD + k0 + kk;
                sm[i] = g_ctx[ci] + g_ctx2[ci];
            }
            __syncthreads();
            const int h = tid >> 6;
            float acc[16];
#pragma unroll
            for (int b = 0; b < 16; b++) acc[b] = 0.f;
#pragma unroll
            for (int kk = 0; kk < 16; kk++) {
                float w = wvc[(size_t)(k0 + kk) * DD + tid];
#pragma unroll
                for (int b = 0; b < 16; b++)
                    acc[b] = fmaf(sm[(b * 16 + h) * 16 + kk], w, acc[b]);
            }
            float* pb = g_part + (size_t)task * BB * DD + tid;
#pragma unroll
            for (int b = 0; b < 16; b++) pb[b * DD] = acc[b];
            __syncthreads();
        }
        GSYNC();

        // ---- P13: reduce vproj + bias -> g_attn ----
        for (int task = bx; task < 16; task += GRID) {
            float v = 0.f;
#pragma unroll 8
            for (int ks = 0; ks < 64; ks++)
                v += g_part[(size_t)(ks * 16 + task) * DD + tid];
            g_attn[task * DD + tid] = v + bvc[tid];
        }
        GSYNC();

        // ---- P14/P15: wo_c GEMM + reduce/LN2 ----
        gemmDD(g_attn, woc, bx, tid, sm);
        GSYNC();
        ln_red(64, boc, P.ln2g + vo, P.ln2b + vo, bx, tid, sm);
        GSYNC();

        // ---- P16: FFN1 partials (128 tasks) ----
        for (int task = bx; task < 128; task += GRID) {
            const int cc = task >> 5, ks = task & 31, k0 = ks * 32;
            if (tid < 512) sm[tid] = g_x[(tid >> 5) * DD + k0 + (tid & 31)];
            __syncthreads();
            const int n = cc * 1024 + tid;
            float acc[16];
#pragma unroll
            for (int b = 0; b < 16; b++) acc[b] = 0.f;
#pragma unroll 8
            for (int kk = 0; kk < 32; kk++) {
                float w = w1l[(size_t)(k0 + kk) * FFD + n];
#pragma unroll
                for (int b = 0; b < 16; b++) acc[b] = fmaf(sm[b * 32 + kk], w, acc[b]);
            }
            float* pb = g_part + (size_t)ks * BB * FFD + n;
#pragma unroll
            for (int b = 0; b < 16; b++) pb[(size_t)b * FFD] = acc[b];
            __syncthreads();
        }
        GSYNC();

        // ---- P17: reduce + bias + relu -> g_hbuf ----
        for (int task = bx; task < 64; task += GRID) {
            const int idx = task * NT + tid;
            const int b = idx >> 12, n = idx & 4095;
            float v = 0.f;
#pragma unroll 8
            for (int ks = 0; ks < 32; ks++)
                v += g_part[(size_t)(ks * 16 + b) * FFD + n];
            v += b1l[n];
            g_hbuf[b * FFD + n] = fmaxf(v, 0.f);
        }
        GSYNC();

        // ---- P18: FFN2 partials (128 tasks) ----
        for (int task = bx; task < 128; task += GRID) {
            const int k0 = task * 32;
            if (tid < 512) sm[tid] = g_hbuf[(tid >> 5) * FFD + k0 + (tid & 31)];
            __syncthreads();
            float acc[16];
#pragma unroll
            for (int b = 0; b < 16; b++) acc[b] = 0.f;
#pragma unroll 8
            for (int kk = 0; kk < 32; kk++) {
                float w = w2l[(size_t)(k0 + kk) * DD + tid];
#pragma unroll
                for (int b = 0; b < 16; b++) acc[b] = fmaf(sm[b * 32 + kk], w, acc[b]);
            }
            float* pb = g_part + (size_t)task * BB * DD + tid;
#pragma unroll
            for (int b = 0; b < 16; b++) pb[b * DD] = acc[b];
            __syncthreads();
        }
        GSYNC();

        // ---- P19: reduce + LN3 ----
        ln_red(128, b2l, P.ln3g + vo, P.ln3b + vo, bx, tid, sm);
        GSYNC();
    }

    // ---- final logits ----
    for (int task = bx; task < 16; task += GRID) {
        if (warp < VOUT) {
            float a = 0.f;
            for (int d = lane; d < DD; d += 32)
                a = fmaf(g_x[task * DD + d], P.wout[(size_t)d * VOUT + warp], a);
#pragma unroll
            for (int o = 16; o; o >>= 1) a += __shfl_xor_sync(0xffffffffu, a, o);
            if (lane == 0) P.out[task * VOUT + warp] = a + P.bout[warp];
        }
    }
}

// ===========================================================================
extern "C" void kernel_launch(void* const* d_in, const int* in_sizes, int n_in,
                              void* d_out, int out_size) {
    KP p;
    p.x    = (const float*)d_in[0];
    p.enc  = (const float*)d_in[1];
    p.kc   = (const float*)d_in[2];
    p.vc   = (const float*)d_in[3];
    p.wq_s = (const float*)d_in[4];  p.bq_s = (const float*)d_in[5];
    p.wk_s = (const float*)d_in[6];  p.bk_s = (const float*)d_in[7];
    p.wv_s = (const float*)d_in[8];  p.bv_s = (const float*)d_in[9];
    p.wo_s = (const float*)d_in[10]; p.bo_s = (const float*)d_in[11];
    p.wq_c = (const float*)d_in[12]; p.bq_c = (const float*)d_in[13];
    p.wk_c = (const float*)d_in[14]; p.bk_c = (const float*)d_in[15];
    p.wv_c = (const float*)d_in[16]; p.bv_c = (const float*)d_in[17];
    p.wo_c = (const float*)d_in[18]; p.bo_c = (const float*)d_in[19];
    p.w1   = (const float*)d_in[20]; p.b1   = (const float*)d_in[21];
    p.w2   = (const float*)d_in[22]; p.b2   = (const float*)d_in[23];
    p.ln1g = (const float*)d_in[24]; p.ln1b = (const float*)d_in[25];
    p.ln2g = (const float*)d_in[26]; p.ln2b = (const float*)d_in[27];
    p.ln3g = (const float*)d_in[28]; p.ln3b = (const float*)d_in[29];
    p.wout = (const float*)d_in[30]; p.bout = (const float*)d_in[31];
    p.out  = (float*)d_out;

    reset_bar<<<1, 1>>>();
    mega<<<GRID, NT>>>(p);
}